// round 2
// baseline (speedup 1.0000x reference)
#include <cuda_runtime.h>
#include <cuda_bf16.h>

#define DIM 128
#define MSZ (DIM * DIM)  // 16384 elements per matrix

// U tables: V_j[s] for j=0..8 stored at offset (2^j - 1) + s.  511 matrices.
__device__ __align__(16) float g_U[511 * MSZ];   // ~33.5 MB
__device__ __align__(16) float g_Bm[2 * MSZ];    // scaled skew matrices B = (P - P^T)/64
__device__ __align__(16) float g_X0[2 * MSZ];    // ping
__device__ __align__(16) float g_X1[2 * MSZ];    // pong

// ---------------------------------------------------------------------------
// prep: B = (P - P^T) / 64 ;  X = I + B/16   (Taylor order-16 Horner seed)
// ---------------------------------------------------------------------------
__global__ void k_prep(const float* __restrict__ P) {
    int idx = blockIdx.x * blockDim.x + threadIdx.x;
    if (idx >= 2 * MSZ) return;
    int b = idx >> 14;
    int r = (idx >> 7) & 127;
    int c = idx & 127;
    float h = P[b * MSZ + r * DIM + c] - P[b * MSZ + c * DIM + r];
    float bv = h * (1.0f / 64.0f);
    g_Bm[idx] = bv;
    g_X0[idx] = (r == c ? 1.0f : 0.0f) + bv * (1.0f / 16.0f);
}

// ---------------------------------------------------------------------------
// 64x64 output tile of a 128x128x128 fp32 matmul: C_tile = alpha*(A@B) [+ I]
// 256 threads, 4x4 per thread, K chunks of 16.
// ---------------------------------------------------------------------------
__device__ __forceinline__ void mm64_tile(const float* __restrict__ A,
                                          const float* __restrict__ B,
                                          float* __restrict__ C,
                                          int rowBase, int colBase,
                                          float alpha, bool addI) {
    __shared__ __align__(16) float As[16][64];  // As[k][row]
    __shared__ __align__(16) float Bs[16][64];  // Bs[k][col]
    int t = threadIdx.x;
    int tx = t & 15, ty = t >> 4;
    float acc[4][4];
#pragma unroll
    for (int i = 0; i < 4; i++)
#pragma unroll
        for (int j = 0; j < 4; j++) acc[i][j] = 0.0f;

    for (int kc = 0; kc < DIM; kc += 16) {
        {   // load A tile (64 rows x 16 k), store transposed
            int ar = t >> 2;             // 0..63
            int acg = (t & 3) * 4;       // 0,4,8,12
            float4 av = *(const float4*)&A[(rowBase + ar) * DIM + kc + acg];
            As[acg + 0][ar] = av.x; As[acg + 1][ar] = av.y;
            As[acg + 2][ar] = av.z; As[acg + 3][ar] = av.w;
        }
        {   // load B tile (16 k x 64 cols)
            int br = t >> 4;             // 0..15
            int bcg = (t & 15) * 4;      // 0..60
            *(float4*)&Bs[br][bcg] =
                *(const float4*)&B[(kc + br) * DIM + colBase + bcg];
        }
        __syncthreads();
#pragma unroll
        for (int kk = 0; kk < 16; kk++) {
            float a[4], bb[4];
            *(float4*)a  = *(const float4*)&As[kk][ty * 4];
            *(float4*)bb = *(const float4*)&Bs[kk][tx * 4];
#pragma unroll
            for (int i = 0; i < 4; i++)
#pragma unroll
                for (int j = 0; j < 4; j++) acc[i][j] += a[i] * bb[j];
        }
        __syncthreads();
    }
#pragma unroll
    for (int i = 0; i < 4; i++) {
        int gr = rowBase + ty * 4 + i;
#pragma unroll
        for (int j = 0; j < 4; j++) {
            int gc = colBase + tx * 4 + j;
            float v = alpha * acc[i][j];
            if (addI && gr == gc) v += 1.0f;
            C[gr * DIM + gc] = v;
        }
    }
}

// Horner step: Y = I + alpha * (B @ X).  grid = (4 quadrants, 2 matrices)
__global__ void k_horner(int srcSel, float alpha) {
    int quad = blockIdx.x, b = blockIdx.y;
    const float* X = (srcSel ? g_X1 : g_X0) + b * MSZ;
    float* Y       = (srcSel ? g_X0 : g_X1) + b * MSZ;
    mm64_tile(g_Bm + b * MSZ, X, Y, (quad >> 1) * 64, (quad & 1) * 64, alpha, true);
}

// Squaring: Y = X @ X
__global__ void k_square(int srcSel) {
    int quad = blockIdx.x, b = blockIdx.y;
    const float* X = (srcSel ? g_X1 : g_X0) + b * MSZ;
    float* Y       = (srcSel ? g_X0 : g_X1) + b * MSZ;
    mm64_tile(X, X, Y, (quad >> 1) * 64, (quad & 1) * 64, 1.0f, false);
}

// U[0] = I ; U[1+b] = E_b^T   (V_1[s] = W_s^T)
__global__ void k_init_tables(int srcSel) {
    const float* E = srcSel ? g_X1 : g_X0;
    int idx = blockIdx.x * blockDim.x + threadIdx.x;
    if (idx >= 3 * MSZ) return;
    int m = idx >> 14;
    int r = (idx >> 7) & 127, c = idx & 127;
    if (m == 0) g_U[idx] = (r == c) ? 1.0f : 0.0f;
    else        g_U[m * MSZ + r * DIM + c] = E[(m - 1) * MSZ + c * DIM + r];
}

// level j:  U[offCur + s] = U[1 + (s&1)] @ U[offPrev + (s>>1)]
__global__ void k_ulevel(int offPrev, int offCur) {
    int s = blockIdx.x, quad = blockIdx.y;
    const float* A = g_U + (size_t)(1 + (s & 1)) * MSZ;
    const float* B = g_U + (size_t)(offPrev + (s >> 1)) * MSZ;
    float* C       = g_U + (size_t)(offCur + s) * MSZ;
    mm64_tile(A, B, C, (quad >> 1) * 64, (quad & 1) * 64, 1.0f, false);
}

// ---------------------------------------------------------------------------
// final: one CTA per output position. pos<256 -> table copy; else one matmul
// C = V8[pos&255] @ V_{L-8}[(pos>>8) - 2^{L-8}].  256 thr, 8x8 per thread.
// ---------------------------------------------------------------------------
__global__ void __launch_bounds__(256, 2)
k_final(const int* __restrict__ uniq, float* __restrict__ out) {
    int nidx = blockIdx.x;
    int pos = uniq[nidx];
    float* C = out + (size_t)nidx * MSZ;
    int t = threadIdx.x;

    if (pos < 256) {  // whole map is a precomputed table entry
        int L = 31 - __clz(pos);
        const float* src = g_U + (size_t)(((1 << L) - 1) + (pos - (1 << L))) * MSZ;
        for (int i = t * 4; i < MSZ; i += 256 * 4)
            *(float4*)&C[i] = *(const float4*)&src[i];
        return;
    }

    int q = pos >> 8;                 // 1..255
    int Lq = 31 - __clz(q);
    const float* Am = g_U + (size_t)(255 + (pos & 255)) * MSZ;                // V8 (left)
    const float* Bm = g_U + (size_t)(((1 << Lq) - 1) + (q - (1 << Lq))) * MSZ; // high part (right)

    __shared__ __align__(16) float As[16][128];  // As[k][row] (transposed)
    __shared__ __align__(16) float Bs[16][128];  // Bs[k][col]
    int tx = t & 15, ty = t >> 4;
    float acc[8][8];
#pragma unroll
    for (int i = 0; i < 8; i++)
#pragma unroll
        for (int j = 0; j < 8; j++) acc[i][j] = 0.0f;

    for (int kc = 0; kc < DIM; kc += 16) {
        {   // A tile: 128 rows x 16 k
            int ar = t >> 1;              // 0..127
            int acg = (t & 1) * 8;        // 0 or 8
            float4 a0 = *(const float4*)&Am[ar * DIM + kc + acg];
            float4 a1 = *(const float4*)&Am[ar * DIM + kc + acg + 4];
            As[acg + 0][ar] = a0.x; As[acg + 1][ar] = a0.y;
            As[acg + 2][ar] = a0.z; As[acg + 3][ar] = a0.w;
            As[acg + 4][ar] = a1.x; As[acg + 5][ar] = a1.y;
            As[acg + 6][ar] = a1.z; As[acg + 7][ar] = a1.w;
        }
        {   // B tile: 16 k x 128 cols
            int br = t >> 4;              // 0..15
            int bcg = (t & 15) * 8;       // 0..120
            *(float4*)&Bs[br][bcg]     = *(const float4*)&Bm[(kc + br) * DIM + bcg];
            *(float4*)&Bs[br][bcg + 4] = *(const float4*)&Bm[(kc + br) * DIM + bcg + 4];
        }
        __syncthreads();
#pragma unroll
        for (int kk = 0; kk < 16; kk++) {
            float a[8], bb[8];
            *(float4*)&a[0]  = *(const float4*)&As[kk][ty * 8];
            *(float4*)&a[4]  = *(const float4*)&As[kk][ty * 8 + 4];
            *(float4*)&bb[0] = *(const float4*)&Bs[kk][tx * 8];
            *(float4*)&bb[4] = *(const float4*)&Bs[kk][tx * 8 + 4];
#pragma unroll
            for (int i = 0; i < 8; i++)
#pragma unroll
                for (int j = 0; j < 8; j++) acc[i][j] += a[i] * bb[j];
        }
        __syncthreads();
    }
#pragma unroll
    for (int i = 0; i < 8; i++) {
        int gr = ty * 8 + i;
        float4 v0 = make_float4(acc[i][0], acc[i][1], acc[i][2], acc[i][3]);
        float4 v1 = make_float4(acc[i][4], acc[i][5], acc[i][6], acc[i][7]);
        *(float4*)&C[gr * DIM + tx * 8]     = v0;
        *(float4*)&C[gr * DIM + tx * 8 + 4] = v1;
    }
}

// ---------------------------------------------------------------------------
extern "C" void kernel_launch(void* const* d_in, const int* in_sizes, int n_in,
                              void* d_out, int out_size) {
    const int* uniq = (const int*)d_in[0];          // [8192] int32
    const float* P  = (const float*)d_in[1];        // [2,128,128] float32
    float* out = (float*)d_out;                     // [N,128,128] float32
    int n = in_sizes[0];

    // 1) B = (P - P^T)/64, X = I + B/16
    k_prep<<<(2 * MSZ + 255) / 256, 256>>>(P);

    // 2) Taylor order 16 via Horner: X <- I + (B @ X)/k, k = 15..1
    int sel = 0;
    for (int k = 15; k >= 1; k--) {
        k_horner<<<dim3(4, 2), 256>>>(sel, 1.0f / (float)k);
        sel ^= 1;
    }
    // 3) 6 squarings (undo the /64 scaling): E = X^(2^6)
    for (int i = 0; i < 6; i++) {
        k_square<<<dim3(4, 2), 256>>>(sel);
        sel ^= 1;
    }

    // 4) U[0]=I, U[1..2] = E_b^T
    k_init_tables<<<(3 * MSZ + 255) / 256, 256>>>(sel);

    // 5) build V_j tables, j=2..8 (510 matmuls total, 7 level launches)
    for (int j = 2; j <= 8; j++)
        k_ulevel<<<dim3(1 << j, 4), 256>>>((1 << (j - 1)) - 1, (1 << j) - 1);

    // 6) one 128^3 matmul per output position
    k_final<<<n, 256>>>(uniq, out);
}

// round 4
// speedup vs baseline: 1.8372x; 1.8372x over previous
#include <cuda_runtime.h>
#include <cuda_bf16.h>
#include <cstdint>

#define DIM 128
#define MSZ (DIM * DIM)

// fp32 product tables: entry (pos-1) for pos in [1,512). 511 matrices.
__device__ __align__(16) float g_U[511 * MSZ];
// bf16 split tables, chunked SW128 "smem image" layout, 64KB per matrix:
//   bytes [0,16K)=hi chunk0(k0..63), [16K,32K)=hi chunk1, [32K,48K)=lo c0, [48K,64K)=lo c1
//   g_A16[r] : U[256+r]  stored [m][k]
//   g_B16[i] : U[i+1]    stored [n][k]  (transposed for mma .col operand)
__device__ __align__(1024) __nv_bfloat16 g_A16[256 * 32768];
__device__ __align__(1024) __nv_bfloat16 g_B16[255 * 32768];
// expm scratch
__device__ __align__(16) float g_Bm[2 * MSZ];
__device__ __align__(16) float g_B2[2 * MSZ];
__device__ __align__(16) float g_B3[2 * MSZ];
__device__ __align__(16) float g_B4[2 * MSZ];
__device__ __align__(16) float g_X0[2 * MSZ];
__device__ __align__(16) float g_X1[2 * MSZ];
// global barrier state (monotonic across graph replays; epoch bumped per launch)
__device__ unsigned g_count = 0;
__device__ unsigned g_epoch = 0;

#define SW128(o) ((o) ^ (((o) >> 3) & 0x70))

// ------------------------------------------------------------- PTX helpers
__device__ __forceinline__ uint32_t smem_to_u32(const void* p) {
    uint32_t a;
    asm("{ .reg .u64 t; cvta.to.shared.u64 t, %1; cvt.u32.u64 %0, t; }" : "=r"(a) : "l"(p));
    return a;
}
#define MBARRIER_INIT(addr, cnt) \
    asm volatile("mbarrier.init.shared.b64 [%0], %1;" :: "r"((uint32_t)(addr)), "r"((uint32_t)(cnt)) : "memory")
#define MBARRIER_EXPECT_TX(addr, tx) \
    asm volatile("mbarrier.arrive.expect_tx.shared.b64 _, [%0], %1;" :: "r"((uint32_t)(addr)), "r"((uint32_t)(tx)) : "memory")
#define MBARRIER_WAIT_PARITY(mbar_smem_addr, phase_parity) do { \
    uint32_t _mbar = (uint32_t)(mbar_smem_addr); \
    uint32_t _parity = (uint32_t)(phase_parity); \
    uint32_t _done; \
    asm volatile("{\n\t.reg .pred p;\n\t" \
        "mbarrier.try_wait.parity.acquire.cta.shared::cta.b64 p, [%1], %2;\n\t" \
        "selp.b32 %0, 1, 0, p;\n\t}" : "=r"(_done) : "r"(_mbar), "r"(_parity) : "memory"); \
    if (!_done) { \
        asm volatile("{\n\t.reg .pred P1;\n\t" \
            "WAIT_LOOP_%=:\n\t" \
            "mbarrier.try_wait.parity.acquire.cta.shared::cta.b64 P1, [%0], %1, 0x989680;\n\t" \
            "@P1 bra.uni WAIT_DONE_%=;\n\t" \
            "bra.uni WAIT_LOOP_%=;\n\t" \
            "WAIT_DONE_%=:\n\t}" :: "r"(_mbar), "r"(_parity) : "memory"); \
    } \
} while (0)
__device__ __forceinline__ void bulk_ld(uint32_t dst, const void* src, uint32_t bytes, uint32_t mbar) {
    asm volatile("cp.async.bulk.shared::cta.global.mbarrier::complete_tx::bytes [%0], [%1], %2, [%3];"
                 :: "r"(dst), "l"(src), "r"(bytes), "r"(mbar) : "memory");
}
#define LDSM4(r0, r1, r2, r3, a) \
    asm volatile("ldmatrix.sync.aligned.m8n8.x4.shared.b16 {%0,%1,%2,%3}, [%4];" \
                 : "=r"(r0), "=r"(r1), "=r"(r2), "=r"(r3) : "r"(a))
#define MMA16816(c0, c1, c2, c3, a0, a1, a2, a3, b0, b1) \
    asm volatile("mma.sync.aligned.m16n8k16.row.col.f32.bf16.bf16.f32 " \
                 "{%0,%1,%2,%3}, {%4,%5,%6,%7}, {%8,%9}, {%0,%1,%2,%3};" \
                 : "+f"(c0), "+f"(c1), "+f"(c2), "+f"(c3) \
                 : "r"(a0), "r"(a1), "r"(a2), "r"(a3), "r"(b0), "r"(b1))

// ------------------------------------------------- global barrier (fused kernel)
__device__ __forceinline__ void gbar(unsigned target) {
    __syncthreads();
    if (threadIdx.x == 0) {
        __threadfence();
        atomicAdd(&g_count, 1u);
        unsigned v;
        do {
            asm volatile("ld.acquire.gpu.u32 %0, [%1];" : "=r"(v) : "l"(&g_count) : "memory");
            if ((int)(v - target) >= 0) break;
            __nanosleep(64);
        } while (true);
    }
    __syncthreads();
}

// ------------------------------------- fp32 64x64 tile engine (.cg loads, intra-kernel safe)
__device__ __forceinline__ void mm64cg(const float* __restrict__ A, const float* __restrict__ B,
                                       int rowBase, int colBase, float acc[4][4]) {
    __shared__ __align__(16) float As[16][64];
    __shared__ __align__(16) float Bs[16][64];
    int t = threadIdx.x;
    int tx = t & 15, ty = t >> 4;
#pragma unroll
    for (int i = 0; i < 4; i++)
#pragma unroll
        for (int j = 0; j < 4; j++) acc[i][j] = 0.0f;
    for (int kc = 0; kc < DIM; kc += 16) {
        {
            int ar = t >> 2, acg = (t & 3) * 4;
            float4 av = __ldcg((const float4*)&A[(rowBase + ar) * DIM + kc + acg]);
            As[acg + 0][ar] = av.x; As[acg + 1][ar] = av.y;
            As[acg + 2][ar] = av.z; As[acg + 3][ar] = av.w;
        }
        {
            int br = t >> 4, bcg = (t & 15) * 4;
            *(float4*)&Bs[br][bcg] = __ldcg((const float4*)&B[(kc + br) * DIM + colBase + bcg]);
        }
        __syncthreads();
#pragma unroll
        for (int kk = 0; kk < 16; kk++) {
            float a[4], bb[4];
            *(float4*)a  = *(const float4*)&As[kk][ty * 4];
            *(float4*)bb = *(const float4*)&Bs[kk][tx * 4];
#pragma unroll
            for (int i = 0; i < 4; i++)
#pragma unroll
                for (int j = 0; j < 4; j++) acc[i][j] += a[i] * bb[j];
        }
        __syncthreads();
    }
}
__device__ __forceinline__ void store64(float* __restrict__ C, int rowBase, int colBase,
                                        float acc[4][4]) {
    int tx = threadIdx.x & 15, ty = threadIdx.x >> 4;
#pragma unroll
    for (int i = 0; i < 4; i++)
#pragma unroll
        for (int j = 0; j < 4; j++)
            C[(rowBase + ty * 4 + i) * DIM + colBase + tx * 4 + j] = acc[i][j];
}

// epoch bump (one launch per kernel_launch call)
__global__ void k_epoch() { atomicAdd(&g_epoch, 1u); }

// -------------------------------------------------------------------------
// Fused: prep -> B2,B3,B4 -> Paterson-Stockmeyer deg-16 -> 6 squarings ->
//        init tables -> levels 2..5.   128 CTAs, 17 global barriers.
// -------------------------------------------------------------------------
#define NBAR 17u
__global__ void __launch_bounds__(256) k_fused(const float* __restrict__ P) {
    const int cta = blockIdx.y * 32 + blockIdx.x;   // 0..127
    const int t = threadIdx.x;
    __shared__ unsigned sE;
    if (t == 0) sE = *(volatile unsigned*)&g_epoch;
    __syncthreads();
    const unsigned base = (sE - 1u) * NBAR * 128u;
    int barId = 0;
#define GBAR() gbar(base + (unsigned)(++barId) * 128u)

    // factorial reciprocals
    const float c0 = 1.0f, c1 = 1.0f, c2 = 0.5f, c3 = 1.0f / 6.0f, c4 = 1.0f / 24.0f;
    const float c5 = 1.0f / 120.0f, c6 = 1.0f / 720.0f, c7 = 1.0f / 5040.0f;
    const float c8 = 1.0f / 40320.0f, c9 = 2.75573192e-6f, c10 = 2.75573192e-7f;
    const float c11 = 2.50521084e-8f, c12 = 2.08767570e-9f, c13 = 1.60590438e-10f;
    const float c14 = 1.14707456e-11f, c15 = 7.64716373e-13f, c16 = 4.77947733e-14f;

    // ---- prep: Bm = (P - P^T)/64   (one element per thread)
    {
        int idx = cta * 256 + t;                    // < 32768 = 2*MSZ
        int b = idx >> 14, r = (idx >> 7) & 127, c = idx & 127;
        float h = __ldg(&P[b * MSZ + r * DIM + c]) - __ldg(&P[b * MSZ + c * DIM + r]);
        g_Bm[idx] = h * (1.0f / 64.0f);
    }
    GBAR();
    // ---- B2 = Bm*Bm  (8 CTAs)
    if (cta < 8) {
        int b = cta >> 2, quad = cta & 3;
        int rB = (quad >> 1) * 64, cB = (quad & 1) * 64;
        float acc[4][4];
        mm64cg(g_Bm + b * MSZ, g_Bm + b * MSZ, rB, cB, acc);
        store64(g_B2 + b * MSZ, rB, cB, acc);
    }
    GBAR();
    // ---- B3 = B2*Bm, B4 = B2*B2  (16 CTAs)
    if (cta < 16) {
        int z = cta >> 3, b = (cta >> 2) & 1, quad = cta & 3;
        int rB = (quad >> 1) * 64, cB = (quad & 1) * 64;
        float acc[4][4];
        mm64cg(g_B2 + b * MSZ, (z ? g_B2 : g_Bm) + b * MSZ, rB, cB, acc);
        store64((z ? g_B4 : g_B3) + b * MSZ, rB, cB, acc);
    }
    GBAR();
    // ---- PS init: X0 = c12 I + c13 B + c14 B2 + c15 B3 + c16 B4
    {
        int idx = cta * 256 + t;
        int r = (idx >> 7) & 127, c = idx & 127;
        float v = c13 * __ldcg(&g_Bm[idx]) + c14 * __ldcg(&g_B2[idx]) +
                  c15 * __ldcg(&g_B3[idx]) + c16 * __ldcg(&g_B4[idx]);
        if (r == c) v += c12;
        g_X0[idx] = v;
    }
    GBAR();
    // ---- 3 Horner steps:  Y = T*B4 + (qx I + qy B + qz B2 + qw B3)
    {
        float qs[3][4] = {{c8, c9, c10, c11}, {c4, c5, c6, c7}, {c0, c1, c2, c3}};
        int sel = 0;
        for (int h = 0; h < 3; h++) {
            if (cta < 8) {
                int b = cta >> 2, quad = cta & 3;
                int rB = (quad >> 1) * 64, cB = (quad & 1) * 64;
                const float* T = (sel ? g_X1 : g_X0) + b * MSZ;
                float* Y       = (sel ? g_X0 : g_X1) + b * MSZ;
                float acc[4][4];
                mm64cg(T, g_B4 + b * MSZ, rB, cB, acc);
                int tx = t & 15, ty = t >> 4;
#pragma unroll
                for (int i = 0; i < 4; i++) {
                    int gr = rB + ty * 4 + i;
#pragma unroll
                    for (int j = 0; j < 4; j++) {
                        int gc = cB + tx * 4 + j;
                        int e = b * MSZ + gr * DIM + gc;
                        float v = acc[i][j] + qs[h][1] * __ldcg(&g_Bm[e]) +
                                  qs[h][2] * __ldcg(&g_B2[e]) + qs[h][3] * __ldcg(&g_B3[e]);
                        if (gr == gc) v += qs[h][0];
                        Y[gr * DIM + gc] = v;
                    }
                }
            }
            sel ^= 1;
            GBAR();
        }
        // ---- 6 squarings (X1 holds result after loop: sel=1 start)
        for (int sq = 0; sq < 6; sq++) {
            if (cta < 8) {
                int b = cta >> 2, quad = cta & 3;
                int rB = (quad >> 1) * 64, cB = (quad & 1) * 64;
                const float* X = (sel ? g_X1 : g_X0) + b * MSZ;
                float* Y       = (sel ? g_X0 : g_X1) + b * MSZ;
                float acc[4][4];
                mm64cg(X, X, rB, cB, acc);
                store64(Y, rB, cB, acc);
            }
            sel ^= 1;
            GBAR();
        }
        // after h(3)+sq(6): sel started 0 ->flips 9 times -> sel=1 => result in X1
    }
    // ---- init tables: U[0]=I ; U[1+b]=E_b^T  (E in X1)
    for (int i = cta * 256 + t; i < 3 * MSZ; i += 32768) {
        int m = i >> 14, r = (i >> 7) & 127, c = i & 127;
        if (m == 0) g_U[i] = (r == c) ? 1.0f : 0.0f;
        else        g_U[m * MSZ + r * DIM + c] = __ldcg(&g_X1[(m - 1) * MSZ + c * DIM + r]);
    }
    GBAR();
    // ---- levels 2..5: U[(2^j-1)+s] = U[1+(s&1)] @ U[(2^(j-1)-1)+(s>>1)]
    for (int j = 2; j <= 5; j++) {
        if (cta < (4 << j)) {
            int s = cta >> 2, quad = cta & 3;
            int rB = (quad >> 1) * 64, cB = (quad & 1) * 64;
            const float* A = g_U + (size_t)(1 + (s & 1)) * MSZ;
            const float* B = g_U + (size_t)(((1 << (j - 1)) - 1) + (s >> 1)) * MSZ;
            float* C       = g_U + (size_t)(((1 << j) - 1) + s) * MSZ;
            float acc[4][4];
            mm64cg(A, B, rB, cB, acc);
            store64(C, rB, cB, acc);
        }
        if (j < 5) GBAR();
    }
#undef GBAR
}

// ---- levels 6..8 (wide grids, separate launches; plain loads OK across kernels)
__global__ void __launch_bounds__(256) k_ulevel(int offPrev, int offCur) {
    int s = blockIdx.x, quad = blockIdx.y;
    int rB = (quad >> 1) * 64, cB = (quad & 1) * 64;
    const float* A = g_U + (size_t)(1 + (s & 1)) * MSZ;
    const float* B = g_U + (size_t)(offPrev + (s >> 1)) * MSZ;
    float* C       = g_U + (size_t)(offCur + s) * MSZ;
    float acc[4][4];
    mm64cg(A, B, rB, cB, acc);   // .cg harmless here
    store64(C, rB, cB, acc);
}

// ---- bf16 hi/lo split into chunked-SW128 image layout
__global__ void k_mksplit() {
    int m = blockIdx.x;       // 0..510
    int t = threadIdx.x;      // 256
    if (m < 256) {
        const float* src = g_U + (size_t)(255 + m) * MSZ;
        __nv_bfloat16* dst = g_A16 + (size_t)m * 32768;
        for (int e = t; e < MSZ; e += 256) {
            int row = e >> 7, k = e & 127;
            float v = src[row * DIM + k];
            __nv_bfloat16 hi = __float2bfloat16(v);
            __nv_bfloat16 lo = __float2bfloat16(v - __bfloat162float(hi));
            int idx = (k >> 6) * 8192 + (SW128(row * 128 + (k & 63) * 2) >> 1);
            dst[idx] = hi;
            dst[16384 + idx] = lo;
        }
    } else {
        int i = m - 256;      // matrix U[i+1], stored [n][k]
        const float* src = g_U + (size_t)i * MSZ;
        __nv_bfloat16* dst = g_B16 + (size_t)i * 32768;
        for (int e = t; e < MSZ; e += 256) {
            int n = e >> 7, k = e & 127;
            float v = src[k * DIM + n];
            __nv_bfloat16 hi = __float2bfloat16(v);
            __nv_bfloat16 lo = __float2bfloat16(v - __bfloat162float(hi));
            int idx = (k >> 6) * 8192 + (SW128(n * 128 + (k & 63) * 2) >> 1);
            dst[idx] = hi;
            dst[16384 + idx] = lo;
        }
    }
}

// -------------------------------------------------------------------------
// final: HMMA bf16 3-product split.  256 thr (8 warps), warp w = rows [16w,16w+16).
// smem: [0..64)=mbars, [1024,+64K)=A image, [+64K,+64K)=B image.
// -------------------------------------------------------------------------
#define SM_A 1024
#define SM_B (1024 + 65536)
#define SM_TOTAL (1024 + 131072)

__device__ __forceinline__ void hmma_product(uint32_t sb, int hiA, int hiB,
                                             int m0, int lane, float acc[16][4]) {
    uint32_t abase = sb + SM_A + (uint32_t)hiA * 32768u;
    uint32_t bbase = sb + SM_B + (uint32_t)hiB * 32768u;
    int rowa = (m0 + (lane & 15)) * 128;
    int seg = (lane >> 4) * 16;
    int rowb_l = (lane & 15) * 128;
#pragma unroll
    for (int ks = 0; ks < 8; ks++) {
        uint32_t coff = (uint32_t)(ks >> 2) * 16384u;
        int kw2 = (ks & 3) * 32;
        uint32_t a0, a1, a2, a3;
        LDSM4(a0, a1, a2, a3, abase + coff + (uint32_t)SW128(rowa + kw2 + seg));
#pragma unroll
        for (int ng = 0; ng < 8; ng++) {
            uint32_t b0, b1, b2, b3;
            LDSM4(b0, b1, b2, b3,
                  bbase + coff + (uint32_t)SW128(ng * 2048 + rowb_l + kw2 + seg));
            MMA16816(acc[2 * ng][0], acc[2 * ng][1], acc[2 * ng][2], acc[2 * ng][3],
                     a0, a1, a2, a3, b0, b2);
            MMA16816(acc[2 * ng + 1][0], acc[2 * ng + 1][1], acc[2 * ng + 1][2], acc[2 * ng + 1][3],
                     a0, a1, a2, a3, b1, b3);
        }
    }
}

__global__ void __launch_bounds__(256) k_final(const int* __restrict__ uniq,
                                               float* __restrict__ out) {
    extern __shared__ char smem[];
    int pos = uniq[blockIdx.x];
    float* C = out + (size_t)blockIdx.x * MSZ;
    int t = threadIdx.x;

    if (pos < 256) {   // direct table copy
        const float* src = g_U + (size_t)(pos - 1) * MSZ;
        for (int i = t * 4; i < MSZ; i += 256 * 4)
            *(float4*)&C[i] = *(const float4*)&src[i];
        return;
    }
    int r = pos & 255;
    int qi = (pos >> 8) - 1;

    uint32_t sb = smem_to_u32(smem);
    if (t == 0) {
        MBARRIER_INIT(sb + 0, 1);
        MBARRIER_INIT(sb + 8, 1);
    }
    __syncthreads();
    if (t == 0) {
        const char* As = (const char*)(g_A16 + (size_t)r * 32768);
        const char* Bs = (const char*)(g_B16 + (size_t)qi * 32768);
        MBARRIER_EXPECT_TX(sb + 0, 65536);          // hi halves
        bulk_ld(sb + SM_A, As, 32768, sb + 0);
        bulk_ld(sb + SM_B, Bs, 32768, sb + 0);
        MBARRIER_EXPECT_TX(sb + 8, 65536);          // lo halves
        bulk_ld(sb + SM_A + 32768, As + 32768, 32768, sb + 8);
        bulk_ld(sb + SM_B + 32768, Bs + 32768, 32768, sb + 8);
    }

    int wid = t >> 5, lane = t & 31;
    int m0 = wid * 16;
    float acc[16][4];
#pragma unroll
    for (int i = 0; i < 16; i++)
#pragma unroll
        for (int j = 0; j < 4; j++) acc[i][j] = 0.0f;

    MBARRIER_WAIT_PARITY(sb + 0, 0);
    hmma_product(sb, 0, 0, m0, lane, acc);          // Ahi * Bhi
    MBARRIER_WAIT_PARITY(sb + 8, 0);
    hmma_product(sb, 0, 1, m0, lane, acc);          // Ahi * Blo
    hmma_product(sb, 1, 0, m0, lane, acc);          // Alo * Bhi

    int r0 = m0 + (lane >> 2);
    int cb = (lane & 3) * 2;
#pragma unroll
    for (int nt = 0; nt < 16; nt++) {
        int col = nt * 8 + cb;
        *(float2*)&C[r0 * DIM + col]       = make_float2(acc[nt][0], acc[nt][1]);
        *(float2*)&C[(r0 + 8) * DIM + col] = make_float2(acc[nt][2], acc[nt][3]);
    }
}

// -------------------------------------------------------------------------
extern "C" void kernel_launch(void* const* d_in, const int* in_sizes, int n_in,
                              void* d_out, int out_size) {
    const int* uniq = (const int*)d_in[0];
    const float* P  = (const float*)d_in[1];
    float* out = (float*)d_out;
    int n = in_sizes[0];

    k_epoch<<<1, 1>>>();
    k_fused<<<dim3(32, 4), 256>>>(P);
    k_ulevel<<<dim3(64, 4), 256>>>(31, 63);     // j=6
    k_ulevel<<<dim3(128, 4), 256>>>(63, 127);   // j=7
    k_ulevel<<<dim3(256, 4), 256>>>(127, 255);  // j=8
    k_mksplit<<<511, 256>>>();

    cudaFuncSetAttribute(k_final, cudaFuncAttributeMaxDynamicSharedMemorySize, SM_TOTAL);
    k_final<<<n, 256, SM_TOTAL>>>(uniq, out);
}

// round 5
// speedup vs baseline: 2.2368x; 1.2175x over previous
#include <cuda_runtime.h>
#include <cuda_bf16.h>
#include <cstdint>

#define DIM 128
#define MSZ (DIM * DIM)

// fp32 tables: g_U[e] = map for pos e+1, e in [0,510]. (level 8 fp32 unused/not written)
__device__ __align__(16) float g_U[511 * MSZ];
// bf16 split images, chunked SW128 layout, 64KB (32768 bf16) per matrix:
//   [hi c0 16K][hi c1 16K][lo c0 16K][lo c1 16K]; chunk c covers k in [64c,64c+64)
// g_A16[s] : U[255+s] stored [m][k]   (A-side of final product)
// g_B16[e] : U[e]     stored [n][k]   (B-side / right operand), e in [0,254]
__device__ __align__(1024) __nv_bfloat16 g_A16[256 * 32768];
__device__ __align__(1024) __nv_bfloat16 g_B16[255 * 32768];
// A-side split of U[1], U[2] ([m][k]) for table building
__device__ __align__(1024) __nv_bfloat16 g_AW[2 * 32768];
// expm scratch
__device__ __align__(16) float g_Bm[2 * MSZ];
__device__ __align__(16) float g_B2[2 * MSZ];
__device__ __align__(16) float g_B3[2 * MSZ];
__device__ __align__(16) float g_B4[2 * MSZ];
__device__ __align__(16) float g_X0[2 * MSZ];
__device__ __align__(16) float g_X1[2 * MSZ];
// global barrier state (monotonic across graph replays)
__device__ unsigned g_count = 0;
__device__ unsigned g_epoch = 0;

#define SW128(o) ((o) ^ (((o) >> 3) & 0x70))

// ------------------------------------------------------------- PTX helpers
__device__ __forceinline__ uint32_t smem_to_u32(const void* p) {
    uint32_t a;
    asm("{ .reg .u64 t; cvta.to.shared.u64 t, %1; cvt.u32.u64 %0, t; }" : "=r"(a) : "l"(p));
    return a;
}
#define MBARRIER_INIT(addr, cnt) \
    asm volatile("mbarrier.init.shared.b64 [%0], %1;" :: "r"((uint32_t)(addr)), "r"((uint32_t)(cnt)) : "memory")
#define MBARRIER_EXPECT_TX(addr, tx) \
    asm volatile("mbarrier.arrive.expect_tx.shared.b64 _, [%0], %1;" :: "r"((uint32_t)(addr)), "r"((uint32_t)(tx)) : "memory")
#define MBARRIER_ARRIVE(addr) \
    asm volatile("mbarrier.arrive.shared.b64 _, [%0];" :: "r"((uint32_t)(addr)) : "memory")
#define MBARRIER_WAIT_PARITY(mbar_smem_addr, phase_parity) do { \
    uint32_t _mbar = (uint32_t)(mbar_smem_addr); \
    uint32_t _parity = (uint32_t)(phase_parity); \
    uint32_t _done; \
    asm volatile("{\n\t.reg .pred p;\n\t" \
        "mbarrier.try_wait.parity.acquire.cta.shared::cta.b64 p, [%1], %2;\n\t" \
        "selp.b32 %0, 1, 0, p;\n\t}" : "=r"(_done) : "r"(_mbar), "r"(_parity) : "memory"); \
    if (!_done) { \
        asm volatile("{\n\t.reg .pred P1;\n\t" \
            "WAIT_LOOP_%=:\n\t" \
            "mbarrier.try_wait.parity.acquire.cta.shared::cta.b64 P1, [%0], %1, 0x989680;\n\t" \
            "@P1 bra.uni WAIT_DONE_%=;\n\t" \
            "bra.uni WAIT_LOOP_%=;\n\t" \
            "WAIT_DONE_%=:\n\t}" :: "r"(_mbar), "r"(_parity) : "memory"); \
    } \
} while (0)
__device__ __forceinline__ void bulk_ld(uint32_t dst, const void* src, uint32_t bytes, uint32_t mbar) {
    asm volatile("cp.async.bulk.shared::cta.global.mbarrier::complete_tx::bytes [%0], [%1], %2, [%3];"
                 :: "r"(dst), "l"(src), "r"(bytes), "r"(mbar) : "memory");
}
#define LDSM4(r0, r1, r2, r3, a) \
    asm volatile("ldmatrix.sync.aligned.m8n8.x4.shared.b16 {%0,%1,%2,%3}, [%4];" \
                 : "=r"(r0), "=r"(r1), "=r"(r2), "=r"(r3) : "r"(a))
#define MMA16816(c0, c1, c2, c3, a0, a1, a2, a3, b0, b1) \
    asm volatile("mma.sync.aligned.m16n8k16.row.col.f32.bf16.bf16.f32 " \
                 "{%0,%1,%2,%3}, {%4,%5,%6,%7}, {%8,%9}, {%0,%1,%2,%3};" \
                 : "+f"(c0), "+f"(c1), "+f"(c2), "+f"(c3) \
                 : "r"(a0), "r"(a1), "r"(a2), "r"(a3), "r"(b0), "r"(b1))

// ------------------------------------------------- global barrier (fused kernel)
__device__ __forceinline__ void gbar(unsigned target) {
    __syncthreads();
    if (threadIdx.x == 0) {
        __threadfence();
        atomicAdd(&g_count, 1u);
        unsigned v;
        do {
            asm volatile("ld.acquire.gpu.u32 %0, [%1];" : "=r"(v) : "l"(&g_count) : "memory");
            if ((int)(v - target) >= 0) break;
            __nanosleep(64);
        } while (true);
    }
    __syncthreads();
}

// ------------------------------------- fp32 64x64 tile engine (.cg loads)
__device__ __forceinline__ void mm64cg(const float* __restrict__ A, const float* __restrict__ B,
                                       int rowBase, int colBase, float acc[4][4]) {
    __shared__ __align__(16) float As[16][64];
    __shared__ __align__(16) float Bs[16][64];
    int t = threadIdx.x;
    int tx = t & 15, ty = t >> 4;
#pragma unroll
    for (int i = 0; i < 4; i++)
#pragma unroll
        for (int j = 0; j < 4; j++) acc[i][j] = 0.0f;
    for (int kc = 0; kc < DIM; kc += 16) {
        {
            int ar = t >> 2, acg = (t & 3) * 4;
            float4 av = __ldcg((const float4*)&A[(rowBase + ar) * DIM + kc + acg]);
            As[acg + 0][ar] = av.x; As[acg + 1][ar] = av.y;
            As[acg + 2][ar] = av.z; As[acg + 3][ar] = av.w;
        }
        {
            int br = t >> 4, bcg = (t & 15) * 4;
            *(float4*)&Bs[br][bcg] = __ldcg((const float4*)&B[(kc + br) * DIM + colBase + bcg]);
        }
        __syncthreads();
#pragma unroll
        for (int kk = 0; kk < 16; kk++) {
            float a[4], bb[4];
            *(float4*)a  = *(const float4*)&As[kk][ty * 4];
            *(float4*)bb = *(const float4*)&Bs[kk][tx * 4];
#pragma unroll
            for (int i = 0; i < 4; i++)
#pragma unroll
                for (int j = 0; j < 4; j++) acc[i][j] += a[i] * bb[j];
        }
        __syncthreads();
    }
}
__device__ __forceinline__ void store64(float* __restrict__ C, int rowBase, int colBase,
                                        float acc[4][4]) {
    int tx = threadIdx.x & 15, ty = threadIdx.x >> 4;
#pragma unroll
    for (int i = 0; i < 4; i++)
#pragma unroll
        for (int j = 0; j < 4; j++)
            C[(rowBase + ty * 4 + i) * DIM + colBase + tx * 4 + j] = acc[i][j];
}

__global__ void k_epoch() { atomicAdd(&g_epoch, 1u); }

// -------------------------------------------------------------------------
// Fused: prep -> B2,B3,B4 -> PS deg-16 -> 6 squarings -> init tables ->
//        levels 2..5 -> split (W A-images + levels 0..5 B-images).
// 128 CTAs, 18 global barriers.
// -------------------------------------------------------------------------
#define NBAR 18u
__global__ void __launch_bounds__(256) k_fused(const float* __restrict__ P) {
    const int cta = blockIdx.y * 32 + blockIdx.x;   // 0..127
    const int t = threadIdx.x;
    __shared__ unsigned sE;
    if (t == 0) sE = *(volatile unsigned*)&g_epoch;
    __syncthreads();
    const unsigned base = (sE - 1u) * NBAR * 128u;
    int barId = 0;
#define GBAR() gbar(base + (unsigned)(++barId) * 128u)

    const float c0 = 1.0f, c1 = 1.0f, c2 = 0.5f, c3 = 1.0f / 6.0f, c4 = 1.0f / 24.0f;
    const float c5 = 1.0f / 120.0f, c6 = 1.0f / 720.0f, c7 = 1.0f / 5040.0f;
    const float c8 = 1.0f / 40320.0f, c9 = 2.75573192e-6f, c10 = 2.75573192e-7f;
    const float c11 = 2.50521084e-8f, c12 = 2.08767570e-9f, c13 = 1.60590438e-10f;
    const float c14 = 1.14707456e-11f, c15 = 7.64716373e-13f, c16 = 4.77947733e-14f;

    {   // prep
        int idx = cta * 256 + t;
        int b = idx >> 14, r = (idx >> 7) & 127, c = idx & 127;
        float h = __ldg(&P[b * MSZ + r * DIM + c]) - __ldg(&P[b * MSZ + c * DIM + r]);
        g_Bm[idx] = h * (1.0f / 64.0f);
    }
    GBAR();
    if (cta < 8) {   // B2
        int b = cta >> 2, quad = cta & 3;
        int rB = (quad >> 1) * 64, cB = (quad & 1) * 64;
        float acc[4][4];
        mm64cg(g_Bm + b * MSZ, g_Bm + b * MSZ, rB, cB, acc);
        store64(g_B2 + b * MSZ, rB, cB, acc);
    }
    GBAR();
    if (cta < 16) {  // B3, B4
        int z = cta >> 3, b = (cta >> 2) & 1, quad = cta & 3;
        int rB = (quad >> 1) * 64, cB = (quad & 1) * 64;
        float acc[4][4];
        mm64cg(g_B2 + b * MSZ, (z ? g_B2 : g_Bm) + b * MSZ, rB, cB, acc);
        store64((z ? g_B4 : g_B3) + b * MSZ, rB, cB, acc);
    }
    GBAR();
    {   // PS init
        int idx = cta * 256 + t;
        int r = (idx >> 7) & 127, c = idx & 127;
        float v = c13 * __ldcg(&g_Bm[idx]) + c14 * __ldcg(&g_B2[idx]) +
                  c15 * __ldcg(&g_B3[idx]) + c16 * __ldcg(&g_B4[idx]);
        if (r == c) v += c12;
        g_X0[idx] = v;
    }
    GBAR();
    {
        float qs[3][4] = {{c8, c9, c10, c11}, {c4, c5, c6, c7}, {c0, c1, c2, c3}};
        int sel = 0;
        for (int h = 0; h < 3; h++) {
            if (cta < 8) {
                int b = cta >> 2, quad = cta & 3;
                int rB = (quad >> 1) * 64, cB = (quad & 1) * 64;
                const float* T = (sel ? g_X1 : g_X0) + b * MSZ;
                float* Y       = (sel ? g_X0 : g_X1) + b * MSZ;
                float acc[4][4];
                mm64cg(T, g_B4 + b * MSZ, rB, cB, acc);
                int tx = t & 15, ty = t >> 4;
#pragma unroll
                for (int i = 0; i < 4; i++) {
                    int gr = rB + ty * 4 + i;
#pragma unroll
                    for (int j = 0; j < 4; j++) {
                        int gc = cB + tx * 4 + j;
                        int e = b * MSZ + gr * DIM + gc;
                        float v = acc[i][j] + qs[h][1] * __ldcg(&g_Bm[e]) +
                                  qs[h][2] * __ldcg(&g_B2[e]) + qs[h][3] * __ldcg(&g_B3[e]);
                        if (gr == gc) v += qs[h][0];
                        Y[gr * DIM + gc] = v;
                    }
                }
            }
            sel ^= 1;
            GBAR();
        }
        for (int sq = 0; sq < 6; sq++) {
            if (cta < 8) {
                int b = cta >> 2, quad = cta & 3;
                int rB = (quad >> 1) * 64, cB = (quad & 1) * 64;
                const float* X = (sel ? g_X1 : g_X0) + b * MSZ;
                float* Y       = (sel ? g_X0 : g_X1) + b * MSZ;
                float acc[4][4];
                mm64cg(X, X, rB, cB, acc);
                store64(Y, rB, cB, acc);
            }
            sel ^= 1;
            GBAR();
        }
    }
    // init tables (E in X1)
    for (int i = cta * 256 + t; i < 3 * MSZ; i += 32768) {
        int m = i >> 14, r = (i >> 7) & 127, c = i & 127;
        if (m == 0) g_U[i] = (r == c) ? 1.0f : 0.0f;
        else        g_U[m * MSZ + r * DIM + c] = __ldcg(&g_X1[(m - 1) * MSZ + c * DIM + r]);
    }
    GBAR();
    // levels 2..5
    for (int j = 2; j <= 5; j++) {
        if (cta < (4 << j)) {
            int s = cta >> 2, quad = cta & 3;
            int rB = (quad >> 1) * 64, cB = (quad & 1) * 64;
            const float* A = g_U + (size_t)(1 + (s & 1)) * MSZ;
            const float* B = g_U + (size_t)(((1 << (j - 1)) - 1) + (s >> 1)) * MSZ;
            float* C       = g_U + (size_t)(((1 << j) - 1) + s) * MSZ;
            float acc[4][4];
            mm64cg(A, B, rB, cB, acc);
            store64(C, rB, cB, acc);
        }
        GBAR();
    }
    // split phase: g_AW (U[1],U[2] as [m][k]) + g_B16[0..62] ([n][k])
    for (int item = cta * 256 + t; item < 2 * MSZ; item += 32768) {
        int mat = item >> 14, el = item & 16383, m = el >> 7, k = el & 127;
        float v = __ldcg(&g_U[(size_t)(1 + mat) * MSZ + m * DIM + k]);
        __nv_bfloat16 hi = __float2bfloat16(v);
        __nv_bfloat16 lo = __float2bfloat16(v - __bfloat162float(hi));
        int idx = (k >> 6) * 8192 + (SW128(m * 128 + (k & 63) * 2) >> 1);
        g_AW[mat * 32768 + idx] = hi;
        g_AW[mat * 32768 + 16384 + idx] = lo;
    }
    for (int item = cta * 256 + t; item < 63 * MSZ; item += 32768) {
        int mat = item >> 14, el = item & 16383, n = el & 127, k = el >> 7;
        float v = __ldcg(&g_U[(size_t)mat * MSZ + k * DIM + n]);
        __nv_bfloat16 hi = __float2bfloat16(v);
        __nv_bfloat16 lo = __float2bfloat16(v - __bfloat162float(hi));
        int idx = (k >> 6) * 8192 + (SW128(n * 128 + (k & 63) * 2) >> 1);
        g_B16[(size_t)mat * 32768 + idx] = hi;
        g_B16[(size_t)mat * 32768 + 16384 + idx] = lo;
    }
#undef GBAR
}

// -------------------------------------------------------------------------
// HMMA engine: warp (wr,wc) computes 32 rows x 64 cols of C = Aimg * Bimg.
// aimg/bimg: 32KB half-image (chunk0 @+0, chunk1 @+16K), SW128.
// -------------------------------------------------------------------------
__device__ __forceinline__ void hmma_prod(uint32_t aimg, uint32_t bimg,
                                          int wr, int wc, int lane, float acc[2][8][4]) {
    int rA0 = (wr * 32 + (lane & 15)) * 128;
    int rA1 = rA0 + 16 * 128;
    int seg = (lane >> 4) * 16;
    int rB = (lane & 15) * 128;
#pragma unroll
    for (int ks = 0; ks < 8; ks++) {
        uint32_t coff = (uint32_t)(ks >> 2) * 16384u;
        int kw2 = (ks & 3) * 32;
        uint32_t a0, a1, a2, a3, a4, a5, a6, a7;
        LDSM4(a0, a1, a2, a3, aimg + coff + (uint32_t)SW128(rA0 + kw2 + seg));
        LDSM4(a4, a5, a6, a7, aimg + coff + (uint32_t)SW128(rA1 + kw2 + seg));
#pragma unroll
        for (int ng = 0; ng < 4; ng++) {
            uint32_t b0, b1, b2, b3;
            LDSM4(b0, b1, b2, b3,
                  bimg + coff + (uint32_t)SW128((wc * 4 + ng) * 2048 + rB + kw2 + seg));
            MMA16816(acc[0][2 * ng][0], acc[0][2 * ng][1], acc[0][2 * ng][2], acc[0][2 * ng][3],
                     a0, a1, a2, a3, b0, b2);
            MMA16816(acc[0][2 * ng + 1][0], acc[0][2 * ng + 1][1], acc[0][2 * ng + 1][2], acc[0][2 * ng + 1][3],
                     a0, a1, a2, a3, b1, b3);
            MMA16816(acc[1][2 * ng][0], acc[1][2 * ng][1], acc[1][2 * ng][2], acc[1][2 * ng][3],
                     a4, a5, a6, a7, b0, b2);
            MMA16816(acc[1][2 * ng + 1][0], acc[1][2 * ng + 1][1], acc[1][2 * ng + 1][2], acc[1][2 * ng + 1][3],
                     a4, a5, a6, a7, b1, b3);
        }
    }
}
__device__ __forceinline__ void store_frag(float* __restrict__ C, int wr, int wc, int lane,
                                           float acc[2][8][4]) {
#pragma unroll
    for (int rt = 0; rt < 2; rt++) {
        int row0 = wr * 32 + rt * 16 + (lane >> 2);
#pragma unroll
        for (int ct = 0; ct < 8; ct++) {
            int col = wc * 64 + ct * 8 + (lane & 3) * 2;
            *(float2*)&C[row0 * DIM + col]       = make_float2(acc[rt][ct][0], acc[rt][ct][1]);
            *(float2*)&C[(row0 + 8) * DIM + col] = make_float2(acc[rt][ct][2], acc[rt][ct][3]);
        }
    }
}

// -------------------------------------------------------------------------
// HMMA table levels 6..8: C = W_{s&1} * U[offPrev + s>>1] via split product.
// modeA=0: write fp32 g_U[e] + [n][k] split g_B16[e]; modeA=1: [m][k] split g_A16[e-255].
// smem: [0..64) mbars, [1024, +128K) images / stage.
// -------------------------------------------------------------------------
#define UL_SMEM (1024 + 131072)
__global__ void __launch_bounds__(256) k_ulevel_h(int offPrev, int offCur, int modeA) {
    extern __shared__ char smem[];
    uint32_t sb = smem_to_u32(smem);
    int s = blockIdx.x;
    int t = threadIdx.x, wid = t >> 5, lane = t & 31, wr = wid >> 1, wc = wid & 1;
    int e = offCur + s;
    const char* As = (const char*)g_AW + (size_t)(s & 1) * 65536;
    const char* Bs = (const char*)g_B16 + (size_t)(offPrev + (s >> 1)) * 65536;
    if (t == 0) { MBARRIER_INIT(sb + 0, 1); MBARRIER_INIT(sb + 8, 1); }
    __syncthreads();
    uint32_t AH = sb + 1024, BH = AH + 32768, AL = BH + 32768, BL = AL + 32768;
    if (t == 0) {
        MBARRIER_EXPECT_TX(sb + 0, 65536);
        bulk_ld(AH, As, 32768, sb + 0);
        bulk_ld(BH, Bs, 32768, sb + 0);
        MBARRIER_EXPECT_TX(sb + 8, 65536);
        bulk_ld(AL, As + 32768, 32768, sb + 8);
        bulk_ld(BL, Bs + 32768, 32768, sb + 8);
    }
    float acc[2][8][4];
#pragma unroll
    for (int i = 0; i < 2; i++)
#pragma unroll
        for (int j = 0; j < 8; j++)
#pragma unroll
            for (int k = 0; k < 4; k++) acc[i][j][k] = 0.0f;

    MBARRIER_WAIT_PARITY(sb + 0, 0);
    hmma_prod(AH, BH, wr, wc, lane, acc);
    MBARRIER_WAIT_PARITY(sb + 8, 0);
    hmma_prod(AH, BL, wr, wc, lane, acc);
    hmma_prod(AL, BH, wr, wc, lane, acc);
    __syncthreads();
    float* Cs = (float*)(smem + 1024);
    store_frag(Cs, wr, wc, lane, acc);
    __syncthreads();
    if (!modeA) {
        float* Ug = g_U + (size_t)e * MSZ;
        for (int i = t * 4; i < MSZ; i += 1024)
            *(float4*)&Ug[i] = *(const float4*)&Cs[i];
        __nv_bfloat16* dst = g_B16 + (size_t)e * 32768;
        for (int item = t; item < 2048; item += 256) {
            int n = item & 127, kb = item >> 7;
            __nv_bfloat16 hv[8], lv[8];
#pragma unroll
            for (int kk = 0; kk < 8; kk++) {
                float v = Cs[(kb * 8 + kk) * DIM + n];
                __nv_bfloat16 h = __float2bfloat16(v);
                hv[kk] = h;
                lv[kk] = __float2bfloat16(v - __bfloat162float(h));
            }
            int k0 = kb * 8;
            int idx = (k0 >> 6) * 8192 + (SW128(n * 128 + (k0 & 63) * 2) >> 1);
            *(uint4*)&dst[idx] = *(uint4*)hv;
            *(uint4*)&dst[16384 + idx] = *(uint4*)lv;
        }
    } else {
        __nv_bfloat16* dst = g_A16 + (size_t)(e - 255) * 32768;
        for (int item = t; item < 2048; item += 256) {
            int kb = item & 15, m = item >> 4;
            __nv_bfloat16 hv[8], lv[8];
#pragma unroll
            for (int kk = 0; kk < 8; kk++) {
                float v = Cs[m * DIM + kb * 8 + kk];
                __nv_bfloat16 h = __float2bfloat16(v);
                hv[kk] = h;
                lv[kk] = __float2bfloat16(v - __bfloat162float(h));
            }
            int k0 = kb * 8;
            int idx = (k0 >> 6) * 8192 + (SW128(m * 128 + (k0 & 63) * 2) >> 1);
            *(uint4*)&dst[idx] = *(uint4*)hv;
            *(uint4*)&dst[16384 + idx] = *(uint4*)lv;
        }
    }
}

// -------------------------------------------------------------------------
// Persistent final: 152 CTAs, 8 compute warps + 1 producer warp.
// 3-slot ring, 64KB/slot: [A-half 32K][B-half 32K]. Uses per position: hi, lo.
// -------------------------------------------------------------------------
#define SM_SLOT 1024
#define SLOT_SZ 65536
#define FINAL_SMEM (1024 + 3 * 65536)

__global__ void __launch_bounds__(288) k_final(const int* __restrict__ uniq,
                                               float* __restrict__ out, int n) {
    extern __shared__ char smem[];
    uint32_t sb = smem_to_u32(smem);
    int t = threadIdx.x;
    if (t == 0) {
#pragma unroll
        for (int s = 0; s < 3; s++) {
            MBARRIER_INIT(sb + s * 16, 1);        // full (tx)
            MBARRIER_INIT(sb + s * 16 + 8, 256);  // empty (consumers)
        }
    }
    __syncthreads();

    if (t >= 256) {                 // producer warp
        if (t == 256) {
            unsigned u = 0;
            for (int i = blockIdx.x; i < n; i += gridDim.x) {
                int pos = __ldg(&uniq[i]);
                if (pos < 256) continue;
                int r = pos & 255, qi = (pos >> 8) - 1;
                const char* As = (const char*)g_A16 + (size_t)r * 65536;
                const char* Bs = (const char*)g_B16 + (size_t)qi * 65536;
#pragma unroll
                for (int h = 0; h < 2; h++) {
                    unsigned s = u % 3, rd = u / 3;
                    if (rd > 0) MBARRIER_WAIT_PARITY(sb + s * 16 + 8, (rd - 1) & 1);
                    MBARRIER_EXPECT_TX(sb + s * 16, 65536);
                    bulk_ld(sb + SM_SLOT + s * SLOT_SZ,         As + h * 32768, 32768, sb + s * 16);
                    bulk_ld(sb + SM_SLOT + s * SLOT_SZ + 32768, Bs + h * 32768, 32768, sb + s * 16);
                    u++;
                }
            }
        }
        return;
    }

    int wid = t >> 5, lane = t & 31, wr = wid >> 1, wc = wid & 1;
    unsigned u = 0;
    for (int i = blockIdx.x; i < n; i += gridDim.x) {
        int pos = uniq[i];
        float* C = out + (size_t)i * MSZ;
        if (pos < 256) {
            const float* src = g_U + (size_t)(pos - 1) * MSZ;
            for (int e = t * 4; e < MSZ; e += 1024)
                *(float4*)&C[e] = *(const float4*)&src[e];
            continue;
        }
        unsigned uh = u, ul = u + 1;
        u += 2;
        unsigned sh = uh % 3, rh = uh / 3, sl = ul % 3, rl = ul / 3;
        uint32_t baseH = sb + SM_SLOT + sh * SLOT_SZ;
        uint32_t baseL = sb + SM_SLOT + sl * SLOT_SZ;

        float acc[2][8][4];
#pragma unroll
        for (int a = 0; a < 2; a++)
#pragma unroll
            for (int b = 0; b < 8; b++)
#pragma unroll
                for (int c = 0; c < 4; c++) acc[a][b][c] = 0.0f;

        MBARRIER_WAIT_PARITY(sb + sh * 16, rh & 1);
        hmma_prod(baseH, baseH + 32768, wr, wc, lane, acc);        // Ahi * Bhi
        MBARRIER_WAIT_PARITY(sb + sl * 16, rl & 1);
        hmma_prod(baseH, baseL + 32768, wr, wc, lane, acc);        // Ahi * Blo
        hmma_prod(baseL, baseH + 32768, wr, wc, lane, acc);        // Alo * Bhi
        MBARRIER_ARRIVE(sb + sh * 16 + 8);
        MBARRIER_ARRIVE(sb + sl * 16 + 8);

        store_frag(C, wr, wc, lane, acc);
    }
}

// -------------------------------------------------------------------------
extern "C" void kernel_launch(void* const* d_in, const int* in_sizes, int n_in,
                              void* d_out, int out_size) {
    const int* uniq = (const int*)d_in[0];
    const float* P  = (const float*)d_in[1];
    float* out = (float*)d_out;
    int n = in_sizes[0];

    k_epoch<<<1, 1>>>();
    k_fused<<<dim3(32, 4), 256>>>(P);

    cudaFuncSetAttribute(k_ulevel_h, cudaFuncAttributeMaxDynamicSharedMemorySize, UL_SMEM);
    k_ulevel_h<<<64,  256, UL_SMEM>>>(31, 63, 0);    // level 6
    k_ulevel_h<<<128, 256, UL_SMEM>>>(63, 127, 0);   // level 7
    k_ulevel_h<<<256, 256, UL_SMEM>>>(127, 255, 1);  // level 8

    cudaFuncSetAttribute(k_final, cudaFuncAttributeMaxDynamicSharedMemorySize, FINAL_SMEM);
    k_final<<<152, 288, FINAL_SMEM>>>(uniq, out, n);
}